// round 14
// baseline (speedup 1.0000x reference)
#include <cuda_runtime.h>
#include <cuda_bf16.h>
#include <cstdint>

// ---------------------------------------------------------------------------
// Problem constants
// ---------------------------------------------------------------------------
#define BB   8
#define TT   2048
#define IND  1024
#define HH   1024
#define MM   (BB * TT)          // 16384

// GEMM tiling
#define BM 128
#define BN 128
#define BK 64
#define NTILE (IND / BK)        // 16 ktiles per output tile
#define NS 2                    // pipeline stages
#define NTHR 256                // 8 warps: 2(m) x 4(n), warp tile 64x32 per W
#define NTILES_OUT ((MM / BM) * (HH / BN))   // 1024 output tiles
#define NPERS 148               // persistent CTAs

// Tile layout: 128 rows x 272 B (256 B data + 16 B pad -> conflict-free LDSM)
#define ROWB   272
#define TILEB  (128 * ROWB)     // 34816
#define STAGEB (3 * TILEB)      // A + Wd + Wb = 104448
#define OF_MBAR (NS * STAGEB)   // full[s] at +s*16, empty[s] at +s*16+8
#define SMEM_TOTAL (OF_MBAR + 64)

// Scan chunking
#define CHK 32
#define CL  (TT / CHK)          // 64  (== wm half-tile height)

// ---------------------------------------------------------------------------
// Device scratch: tiled tf32-rounded operands, 272B row stride, plain k order.
// ---------------------------------------------------------------------------
__device__ float  g_Xt [(size_t)(MM / 128) * NTILE * (TILEB / 4)];   // ~71 MB
__device__ float  g_Wdt[(size_t)(HH / 128) * NTILE * (TILEB / 4)];
__device__ float  g_Wbt[(size_t)(HH / 128) * NTILE * (TILEB / 4)];
__device__ float2 g_AB [(size_t)MM * HH];        // (At, Bt) 134 MB
__device__ float2 g_PQ [(size_t)BB * CHK * HH];  // chunk affine summaries

// ---------------------------------------------------------------------------
// helpers
// ---------------------------------------------------------------------------
__device__ __forceinline__ uint32_t smem_u32(const void* p) {
    uint32_t a;
    asm("{ .reg .u64 t; cvta.to.shared.u64 t, %1; cvt.u32.u64 %0, t; }" : "=r"(a) : "l"(p));
    return a;
}

__device__ __forceinline__ float tf32_round(float f) {
    uint32_t r;
    asm("cvt.rna.tf32.f32 %0, %1;" : "=r"(r) : "f"(f));
    return __uint_as_float(r);
}

__device__ __forceinline__ void mma_tf32(float* c, const uint32_t* a,
                                         uint32_t b0, uint32_t b1) {
    asm volatile(
        "mma.sync.aligned.m16n8k8.row.col.f32.tf32.tf32.f32 "
        "{%0,%1,%2,%3}, {%4,%5,%6,%7}, {%8,%9}, {%0,%1,%2,%3};"
        : "+f"(c[0]), "+f"(c[1]), "+f"(c[2]), "+f"(c[3])
        : "r"(a[0]), "r"(a[1]), "r"(a[2]), "r"(a[3]), "r"(b0), "r"(b1));
}

#define LDSM_X4(r0, r1, r2, r3, addr) \
    asm volatile("ldmatrix.sync.aligned.m8n8.x4.shared.b16 {%0,%1,%2,%3}, [%4];" \
                 : "=r"(r0), "=r"(r1), "=r"(r2), "=r"(r3) : "r"(addr))

#define MBAR_INIT(a, c) \
    asm volatile("mbarrier.init.shared.b64 [%0], %1;" :: "r"(a), "r"(c) : "memory")
#define MBAR_EXPECT_TX(a, b) \
    asm volatile("mbarrier.arrive.expect_tx.shared.b64 _, [%0], %1;" \
                 :: "r"(a), "r"(b) : "memory")
#define MBAR_ARRIVE(a) \
    asm volatile("mbarrier.arrive.shared.b64 _, [%0];" :: "r"(a) : "memory")
#define MBAR_INVAL(a) \
    asm volatile("mbarrier.inval.shared.b64 [%0];" :: "r"(a) : "memory")

__device__ __forceinline__ void bulk_g2s(uint32_t dst, const void* src,
                                         uint32_t bytes, uint32_t mbar) {
    asm volatile(
        "cp.async.bulk.shared::cluster.global.mbarrier::complete_tx::bytes "
        "[%0], [%1], %2, [%3];"
        :: "r"(dst), "l"(src), "r"(bytes), "r"(mbar) : "memory");
}

__device__ __forceinline__ void mbar_wait(uint32_t mbar, uint32_t parity) {
    asm volatile(
        "{\n\t.reg .pred P1;\n\t"
        "WAIT_LOOP_%=:\n\t"
        "mbarrier.try_wait.parity.acquire.cta.shared::cta.b64 P1, [%0], %1, 0x989680;\n\t"
        "@P1 bra.uni WAIT_DONE_%=;\n\t"
        "bra.uni WAIT_LOOP_%=;\n\t"
        "WAIT_DONE_%=:\n\t}"
        :: "r"(mbar), "r"(parity) : "memory");
}

// ---------------------------------------------------------------------------
// Kernel 0: fused tf32-round + tile copy for x, Wd, Wb (272B row stride).
// One thread per (row, ktile): 256 B via 16 independent float4 (MLP 16).
// ---------------------------------------------------------------------------
#define NTX (MM * NTILE)        // 262144
#define NTW (HH * NTILE)        // 16384

__global__ void __launch_bounds__(256)
prep_kernel(const float* __restrict__ x, const float* __restrict__ Wd,
            const float* __restrict__ Wb)
{
    int t = blockIdx.x * blockDim.x + threadIdx.x;
    const float* src;
    float* dst;
    if (t < NTX) {
        src = x; dst = g_Xt;
    } else if (t < NTX + NTW) {
        t -= NTX; src = Wd; dst = g_Wdt;
    } else if (t < NTX + 2 * NTW) {
        t -= NTX + NTW; src = Wb; dst = g_Wbt;
    } else return;

    int kt  = t & (NTILE - 1);
    int row = t >> 4;
    int blk = row >> 7;
    int r   = row & 127;

    const float4* s = (const float4*)(src + (size_t)row * IND + kt * BK);
    float4 v[16];
#pragma unroll
    for (int i = 0; i < 16; i++) v[i] = s[i];
#pragma unroll
    for (int i = 0; i < 16; i++) {
        v[i].x = tf32_round(v[i].x); v[i].y = tf32_round(v[i].y);
        v[i].z = tf32_round(v[i].z); v[i].w = tf32_round(v[i].w);
    }
    size_t dstb = (size_t)(blk * NTILE + kt) * TILEB + (size_t)r * ROWB;
    float4* d = (float4*)((char*)dst + dstb);
#pragma unroll
    for (int i = 0; i < 16; i++) d[i] = v[i];
}

// ---------------------------------------------------------------------------
// Kernel 1: persistent TF32 mma.sync dual GEMM. grid = NPERS CTAs; CTA c
// processes output tiles c, c+NPERS, ... with ONE continuous full/empty
// mbarrier pipeline across tiles (stage = gi&1, parity = (gi>>1)&1, gi =
// global (tile,ktile) counter). Fused activation + chunk-affine epilogue.
// ---------------------------------------------------------------------------
__global__ void __launch_bounds__(NTHR, 1)
gemm_mma_kernel(const float* __restrict__ A_log)
{
    extern __shared__ __align__(128) char smem[];
    const uint32_t sb = smem_u32(smem);
    const int tid  = threadIdx.x;
    const int warp = tid >> 5;
    const int lane = tid & 31;
    const int wm   = warp >> 2;          // 0..1
    const int wn   = warp & 3;           // 0..3
    const int grp  = lane >> 2;          // 0..7
    const int tig  = lane & 3;           // 0..3
    const int mid  = lane >> 3;          // matrix id 0..3 within LDSM.x4
    const int l8   = lane & 7;           // row within matrix
    const int bid  = blockIdx.x;

    const int ntq = (NTILES_OUT - bid + NPERS - 1) / NPERS;  // tiles for this CTA
    const int NIT = ntq * NTILE;

    if (tid == 0) {
#pragma unroll
        for (int s = 0; s < NS; s++) {
            MBAR_INIT(sb + OF_MBAR + s * 16, 1);       // full: tx-based
            MBAR_INIT(sb + OF_MBAR + s * 16 + 8, 8);   // empty: 8 warp arrivals
        }
    }
    __syncthreads();

    // producer load of pipeline slot gi
    auto issue_load = [&](int gi) {
        int q    = gi >> 4;
        int kt   = gi & (NTILE - 1);
        int tile = bid + q * NPERS;
        int mb   = tile >> 3;
        int nb   = tile & 7;
        uint32_t stg = sb + (gi & 1) * STAGEB;
        uint32_t fb  = sb + OF_MBAR + (gi & 1) * 16;
        MBAR_EXPECT_TX(fb, (uint32_t)STAGEB);
        bulk_g2s(stg,             (const char*)g_Xt  + (size_t)(mb * NTILE + kt) * TILEB, TILEB, fb);
        bulk_g2s(stg + TILEB,     (const char*)g_Wdt + (size_t)(nb * NTILE + kt) * TILEB, TILEB, fb);
        bulk_g2s(stg + 2 * TILEB, (const char*)g_Wbt + (size_t)(nb * NTILE + kt) * TILEB, TILEB, fb);
    };

    // prologue: fill both stages
    if (tid == 0) {
        issue_load(0);
        issue_load(1);
    }

    float acc[2][4][4][4];               // [W][mi][ni][c] -> 128 regs

    // Per-lane LDSM role offsets (within a stage), hoisted.
    int aOff[4], dOff[2], bOff[2];
#pragma unroll
    for (int mi = 0; mi < 4; mi++) {
        int r = wm * 64 + mi * 16 + (mid & 1) * 8 + l8;
        aOff[mi] = r * ROWB + (mid >> 1) * 16;
    }
#pragma unroll
    for (int p = 0; p < 2; p++) {
        int r = wn * 32 + (p * 2 + (mid >> 1)) * 8 + l8;
        int off = r * ROWB + (mid & 1) * 16;
        dOff[p] = TILEB + off;
        bOff[p] = 2 * TILEB + off;
    }

    const int lead = (lane == 0);        // one arrival per warp
    const unsigned FULL = 0xffffffffu;

    for (int gi = 0; gi < NIT; gi++) {
        const uint32_t par = (uint32_t)((gi >> 1) & 1);
        const uint32_t fb = sb + OF_MBAR + (gi & 1) * 16;
        const uint32_t eb = fb + 8;

        if ((gi & (NTILE - 1)) == 0) {   // new output tile: reset accumulators
#pragma unroll
            for (int w = 0; w < 2; w++)
#pragma unroll
                for (int mi = 0; mi < 4; mi++)
#pragma unroll
                    for (int ni = 0; ni < 4; ni++)
#pragma unroll
                        for (int c = 0; c < 4; c++) acc[w][mi][ni][c] = 0.f;
        }

        mbar_wait(fb, par);              // stage data ready

        const uint32_t sbase = sb + (gi & 1) * STAGEB;
        uint32_t aA[4], aD[2], aB2[2];
#pragma unroll
        for (int mi = 0; mi < 4; mi++) aA[mi] = sbase + aOff[mi];
#pragma unroll
        for (int p = 0; p < 2; p++) { aD[p] = sbase + dOff[p]; aB2[p] = sbase + bOff[p]; }

#pragma unroll
        for (int g = 0; g < 8; g++) {
            uint32_t af[4][4];
#pragma unroll
            for (int mi = 0; mi < 4; mi++)
                LDSM_X4(af[mi][0], af[mi][1], af[mi][2], af[mi][3], aA[mi] + g * 32);
            uint32_t wd[2][4], wb[2][4];
#pragma unroll
            for (int p = 0; p < 2; p++) {
                LDSM_X4(wd[p][0], wd[p][1], wd[p][2], wd[p][3], aD[p] + g * 32);
                LDSM_X4(wb[p][0], wb[p][1], wb[p][2], wb[p][3], aB2[p] + g * 32);
            }
#pragma unroll
            for (int ni = 0; ni < 4; ni++) {
                const int p  = ni >> 1;
                const int ix = (ni & 1) * 2;
                uint32_t bd0 = wd[p][ix], bd1 = wd[p][ix + 1];
                uint32_t bb0 = wb[p][ix], bb1 = wb[p][ix + 1];
#pragma unroll
                for (int mi = 0; mi < 4; mi++) {
                    mma_tf32(acc[0][mi][ni], af[mi], bd0, bd1);
                    mma_tf32(acc[1][mi][ni], af[mi], bb0, bb1);
                }
            }
        }

        // this warp is done reading the stage (ldmatrix is synchronous)
        if (lead) MBAR_ARRIVE(eb);

        // producer: refill this slot for gi+2 (possibly next output tile)
        if (gi + NS < NIT && tid == 0) {
            mbar_wait(eb, par);          // all 8 warps released the slot
            issue_load(gi + NS);
        }

        if ((gi & (NTILE - 1)) == NTILE - 1) {
            // ---------------------------------------------------------------
            // Epilogue for the completed output tile: fused softplus/exp ->
            // (At, Bt) + chunk affine (P,Q) via shfl scans. expA in registers.
            // ---------------------------------------------------------------
            const int tile = bid + (gi >> 4) * NPERS;
            const int m0 = (tile >> 3) * BM;
            const int n0 = (tile & 7) * BN;

            float ea[4][2];
#pragma unroll
            for (int ni = 0; ni < 4; ni++) {
                int colLoc = wn * 32 + ni * 8 + 2 * tig;
                ea[ni][0] = __expf(__ldg(A_log + n0 + colLoc));
                ea[ni][1] = __expf(__ldg(A_log + n0 + colLoc + 1));
            }

            float Pc[8], Qc[8];
#pragma unroll
            for (int c = 0; c < 8; c++) { Pc[c] = 1.f; Qc[c] = 0.f; }

#pragma unroll
            for (int mi = 0; mi < 4; mi++) {
#pragma unroll
                for (int half = 0; half < 2; half++) {
#pragma unroll
                    for (int ni = 0; ni < 4; ni++) {
                        int colLoc = wn * 32 + ni * 8 + 2 * tig;
                        int row = m0 + wm * 64 + mi * 16 + half * 8 + grp;
                        float zd0 = acc[0][mi][ni][half * 2 + 0];
                        float zd1 = acc[0][mi][ni][half * 2 + 1];
                        float zb0 = acc[1][mi][ni][half * 2 + 0];
                        float zb1 = acc[1][mi][ni][half * 2 + 1];
                        float d0 = fmaxf(zd0, 0.f) + __logf(1.f + __expf(-fabsf(zd0)));
                        float d1 = fmaxf(zd1, 0.f) + __logf(1.f + __expf(-fabsf(zd1)));
                        float a0 = __expf(-d0 * ea[ni][0]);
                        float a1 = __expf(-d1 * ea[ni][1]);
                        float b0 = d0 * zb0;
                        float b1 = d1 * zb1;
                        *(float4*)(&g_AB[(size_t)row * HH + (n0 + colLoc)]) =
                            make_float4(a0, b0, a1, b1);

                        // segment scan over grp for the two columns
                        float P0 = a0, Q0 = b0, P1 = a1, Q1 = b1;
#pragma unroll
                        for (int d = 1; d < 8; d <<= 1) {
                            float Pi0 = __shfl_up_sync(FULL, P0, 4 * d);
                            float Qi0 = __shfl_up_sync(FULL, Q0, 4 * d);
                            float Pi1 = __shfl_up_sync(FULL, P1, 4 * d);
                            float Qi1 = __shfl_up_sync(FULL, Q1, 4 * d);
                            if (grp >= d) {
                                Q0 = fmaf(P0, Qi0, Q0); P0 *= Pi0;
                                Q1 = fmaf(P1, Qi1, Q1); P1 *= Pi1;
                            }
                        }
                        float Ps0 = __shfl_sync(FULL, P0, tig + 28);
                        float Qs0 = __shfl_sync(FULL, Q0, tig + 28);
                        float Ps1 = __shfl_sync(FULL, P1, tig + 28);
                        float Qs1 = __shfl_sync(FULL, Q1, tig + 28);
                        int col = ni * 2;
                        Qc[col]     = fmaf(Ps0, Qc[col],     Qs0); Pc[col]     *= Ps0;
                        Qc[col + 1] = fmaf(Ps1, Qc[col + 1], Qs1); Pc[col + 1] *= Ps1;
                    }
                }
            }

            // grp==0 lanes write the chunk summaries
            if (grp == 0) {
                int bglob  = m0 / TT;
                int cchunk = ((m0 % TT) >> 6) + wm;
                int bc     = bglob * CHK + cchunk;
#pragma unroll
                for (int col = 0; col < 8; col++) {
                    int h = n0 + wn * 32 + (col >> 1) * 8 + 2 * tig + (col & 1);
                    g_PQ[(size_t)bc * HH + h] = make_float2(Pc[col], Qc[col]);
                }
            }
        }
    }

    __syncthreads();
    if (tid == 0) {
#pragma unroll
        for (int s = 0; s < NS; s++) {
            MBAR_INVAL(sb + OF_MBAR + s * 16);
            MBAR_INVAL(sb + OF_MBAR + s * 16 + 8);
        }
    }
}

// ---------------------------------------------------------------------------
// Scan pass 3 (pass2 fused): compute this chunk's start state by folding the
// prior chunk summaries (uniform c per block, 4-way load batching), then
// replay the chunk with fused tanh and write out.
// ---------------------------------------------------------------------------
__global__ void __launch_bounds__(256)
scan_pass3(float* __restrict__ out)
{
    const int idx = blockIdx.x * blockDim.x + threadIdx.x;
    const int h   = idx & (HH - 1);
    const int bc  = idx >> 10;
    const int c   = bc & (CHK - 1);      // uniform within the block
    const int b   = bc >> 5;

    // h0 = fold of chunk summaries 0..c-1 for this (b, h)
    const float2* __restrict__ pqb = g_PQ + (size_t)b * CHK * HH + h;
    float hs = 0.f;
    {
        int cc = 0;
        for (; cc + 4 <= c; cc += 4) {
            float2 v0 = pqb[(size_t)(cc + 0) * HH];
            float2 v1 = pqb[(size_t)(cc + 1) * HH];
            float2 v2 = pqb[(size_t)(cc + 2) * HH];
            float2 v3 = pqb[(size_t)(cc + 3) * HH];
            hs = fmaf(v0.x, hs, v0.y);
            hs = fmaf(v1.x, hs, v1.y);
            hs = fmaf(v2.x, hs, v2.y);
            hs = fmaf(v3.x, hs, v3.y);
        }
        for (; cc < c; cc++) {
            float2 v = pqb[(size_t)cc * HH];
            hs = fmaf(v.x, hs, v.y);
        }
    }

    const float2* __restrict__ p = g_AB + ((size_t)b * TT + (size_t)c * CL) * HH + h;
    float* __restrict__ o        = out  + ((size_t)b * TT + (size_t)c * CL) * HH + h;

    const int U = 8;
    float2 cur[U], nxt[U];
#pragma unroll
    for (int i = 0; i < U; i++) cur[i] = p[(size_t)i * HH];

    for (int t0 = 0; t0 < CL; t0 += U) {
        int tn = t0 + U;
        if (tn < CL) {
#pragma unroll
            for (int i = 0; i < U; i++) nxt[i] = p[(size_t)(tn + i) * HH];
        }
#pragma unroll
        for (int i = 0; i < U; i++) {
            hs = fmaf(cur[i].x, hs, cur[i].y);
            float e  = __expf(-2.f * fabsf(hs));
            float th = __fdividef(1.f - e, 1.f + e);
            o[(size_t)(t0 + i) * HH] = copysignf(th, hs);
        }
#pragma unroll
        for (int i = 0; i < U; i++) cur[i] = nxt[i];
    }
}

// ---------------------------------------------------------------------------
extern "C" void kernel_launch(void* const* d_in, const int* in_sizes, int n_in,
                              void* d_out, int out_size)
{
    const float* x     = (const float*)d_in[0];
    const float* Wd    = (const float*)d_in[1];
    const float* Wb    = (const float*)d_in[2];
    const float* A_log = (const float*)d_in[3];
    float* out         = (float*)d_out;

    // fused tf32-round + tile pre-pass (MLP-16 per thread)
    {
        int nt = NTX + 2 * NTW;
        prep_kernel<<<(nt + 255) / 256, 256>>>(x, Wd, Wb);
    }

    cudaFuncSetAttribute(gemm_mma_kernel,
                         cudaFuncAttributeMaxDynamicSharedMemorySize, SMEM_TOTAL);
    gemm_mma_kernel<<<NPERS, NTHR, SMEM_TOTAL>>>(A_log);

    scan_pass3<<<(BB * CHK * HH) / 256, 256>>>(out);
}

// round 15
// speedup vs baseline: 1.3130x; 1.3130x over previous
#include <cuda_runtime.h>
#include <cuda_bf16.h>
#include <cstdint>

// ---------------------------------------------------------------------------
// Problem constants
// ---------------------------------------------------------------------------
#define BB   8
#define TT   2048
#define IND  1024
#define HH   1024
#define MM   (BB * TT)          // 16384

// GEMM tiling
#define BM 128
#define BN 128
#define BK 64
#define NTILE (IND / BK)        // 16
#define NS 2                    // pipeline stages
#define NTHR 256                // 8 warps: 2(m) x 4(n), warp tile 64x32 per W

// Tile layout: 128 rows x 272 B (256 B data + 16 B pad -> conflict-free LDSM)
#define ROWB   272
#define TILEB  (128 * ROWB)     // 34816
#define STAGEB (3 * TILEB)      // A + Wd + Wb = 104448
#define OF_MBAR (NS * STAGEB)   // full[s] at +s*16, empty[s] at +s*16+8
#define OF_EXPA (OF_MBAR + 64)
#define SMEM_TOTAL (OF_EXPA + BN * 4 + 64)

// Scan chunking
#define CHK 32
#define CL  (TT / CHK)          // 64  (== wm half-tile height)

// ---------------------------------------------------------------------------
// Device scratch: tiled tf32-rounded operands, 272B row stride, plain k order.
// ---------------------------------------------------------------------------
__device__ float  g_Xt [(size_t)(MM / 128) * NTILE * (TILEB / 4)];   // ~71 MB
__device__ float  g_Wdt[(size_t)(HH / 128) * NTILE * (TILEB / 4)];
__device__ float  g_Wbt[(size_t)(HH / 128) * NTILE * (TILEB / 4)];
__device__ float2 g_AB [(size_t)MM * HH];        // (At, Bt) 134 MB
__device__ float2 g_PQ [(size_t)BB * CHK * HH];  // chunk affine summaries

// ---------------------------------------------------------------------------
// helpers
// ---------------------------------------------------------------------------
__device__ __forceinline__ uint32_t smem_u32(const void* p) {
    uint32_t a;
    asm("{ .reg .u64 t; cvta.to.shared.u64 t, %1; cvt.u32.u64 %0, t; }" : "=r"(a) : "l"(p));
    return a;
}

__device__ __forceinline__ float tf32_round(float f) {
    uint32_t r;
    asm("cvt.rna.tf32.f32 %0, %1;" : "=r"(r) : "f"(f));
    return __uint_as_float(r);
}

__device__ __forceinline__ void mma_tf32(float* c, const uint32_t* a,
                                         uint32_t b0, uint32_t b1) {
    asm volatile(
        "mma.sync.aligned.m16n8k8.row.col.f32.tf32.tf32.f32 "
        "{%0,%1,%2,%3}, {%4,%5,%6,%7}, {%8,%9}, {%0,%1,%2,%3};"
        : "+f"(c[0]), "+f"(c[1]), "+f"(c[2]), "+f"(c[3])
        : "r"(a[0]), "r"(a[1]), "r"(a[2]), "r"(a[3]), "r"(b0), "r"(b1));
}

#define LDSM_X4(r0, r1, r2, r3, addr) \
    asm volatile("ldmatrix.sync.aligned.m8n8.x4.shared.b16 {%0,%1,%2,%3}, [%4];" \
                 : "=r"(r0), "=r"(r1), "=r"(r2), "=r"(r3) : "r"(addr))

#define MBAR_INIT(a, c) \
    asm volatile("mbarrier.init.shared.b64 [%0], %1;" :: "r"(a), "r"(c) : "memory")
#define MBAR_EXPECT_TX(a, b) \
    asm volatile("mbarrier.arrive.expect_tx.shared.b64 _, [%0], %1;" \
                 :: "r"(a), "r"(b) : "memory")
#define MBAR_ARRIVE(a) \
    asm volatile("mbarrier.arrive.shared.b64 _, [%0];" :: "r"(a) : "memory")
#define MBAR_INVAL(a) \
    asm volatile("mbarrier.inval.shared.b64 [%0];" :: "r"(a) : "memory")

__device__ __forceinline__ void bulk_g2s(uint32_t dst, const void* src,
                                         uint32_t bytes, uint32_t mbar) {
    asm volatile(
        "cp.async.bulk.shared::cluster.global.mbarrier::complete_tx::bytes "
        "[%0], [%1], %2, [%3];"
        :: "r"(dst), "l"(src), "r"(bytes), "r"(mbar) : "memory");
}

__device__ __forceinline__ void mbar_wait(uint32_t mbar, uint32_t parity) {
    asm volatile(
        "{\n\t.reg .pred P1;\n\t"
        "WAIT_LOOP_%=:\n\t"
        "mbarrier.try_wait.parity.acquire.cta.shared::cta.b64 P1, [%0], %1, 0x989680;\n\t"
        "@P1 bra.uni WAIT_DONE_%=;\n\t"
        "bra.uni WAIT_LOOP_%=;\n\t"
        "WAIT_DONE_%=:\n\t}"
        :: "r"(mbar), "r"(parity) : "memory");
}

// ---------------------------------------------------------------------------
// Kernel 0: fused tf32-round + tile copy for x, Wd, Wb (272B row stride).
// One thread per (row, kt, quarter): 4 independent float4 (MLP 4, 16 data regs).
// ---------------------------------------------------------------------------
#define NTX (MM * 64)           // 4 quarters x 16 ktiles per row
#define NTW (HH * 64)

__global__ void __launch_bounds__(256)
prep_kernel(const float* __restrict__ x, const float* __restrict__ Wd,
            const float* __restrict__ Wb)
{
    int t = blockIdx.x * blockDim.x + threadIdx.x;
    const float* src;
    float* dst;
    if (t < NTX) {
        src = x; dst = g_Xt;
    } else if (t < NTX + NTW) {
        t -= NTX; src = Wd; dst = g_Wdt;
    } else if (t < NTX + 2 * NTW) {
        t -= NTX + NTW; src = Wb; dst = g_Wbt;
    } else return;

    int g   = t & 3;                    // quarter within the 256B ktile row
    int kt  = (t >> 2) & (NTILE - 1);
    int row = t >> 6;
    int blk = row >> 7;
    int r   = row & 127;

    const float4* s = (const float4*)(src + (size_t)row * IND + kt * BK + g * 16);
    float4 v0 = s[0], v1 = s[1], v2 = s[2], v3 = s[3];
    v0.x = tf32_round(v0.x); v0.y = tf32_round(v0.y);
    v0.z = tf32_round(v0.z); v0.w = tf32_round(v0.w);
    v1.x = tf32_round(v1.x); v1.y = tf32_round(v1.y);
    v1.z = tf32_round(v1.z); v1.w = tf32_round(v1.w);
    v2.x = tf32_round(v2.x); v2.y = tf32_round(v2.y);
    v2.z = tf32_round(v2.z); v2.w = tf32_round(v2.w);
    v3.x = tf32_round(v3.x); v3.y = tf32_round(v3.y);
    v3.z = tf32_round(v3.z); v3.w = tf32_round(v3.w);

    size_t dstb = (size_t)(blk * NTILE + kt) * TILEB + (size_t)r * ROWB + g * 64;
    float4* d = (float4*)((char*)dst + dstb);
    d[0] = v0; d[1] = v1; d[2] = v2; d[3] = v3;
}

// ---------------------------------------------------------------------------
// Kernel 1: TF32 mma.sync dual GEMM via ldmatrix, cp.async.bulk 2-stage
// full/empty mbarrier pipeline, fused activation + chunk-affine (pass1)
// epilogue. 256 threads = 8 warps in 2(m) x 4(n); warp tile 64x32 per W.
// (Gridded launch: wave scheduling gives inter-CTA L2 reuse of A tiles.)
// ---------------------------------------------------------------------------
__global__ void __launch_bounds__(NTHR, 1)
gemm_mma_kernel(const float* __restrict__ A_log)
{
    extern __shared__ __align__(128) char smem[];
    const uint32_t sb = smem_u32(smem);
    const int tid  = threadIdx.x;
    const int warp = tid >> 5;
    const int lane = tid & 31;
    const int wm   = warp >> 2;          // 0..1
    const int wn   = warp & 3;           // 0..3
    const int grp  = lane >> 2;          // 0..7
    const int tig  = lane & 3;           // 0..3
    const int mid  = lane >> 3;          // matrix id 0..3 within LDSM.x4
    const int l8   = lane & 7;           // row within matrix
    const int n0   = blockIdx.x * BN;
    const int m0   = blockIdx.y * BM;
    const int mb   = blockIdx.y;
    const int nb   = blockIdx.x;

    if (tid == 0) {
#pragma unroll
        for (int s = 0; s < NS; s++) {
            MBAR_INIT(sb + OF_MBAR + s * 16, 1);       // full: tx-based
            MBAR_INIT(sb + OF_MBAR + s * 16 + 8, 8);   // empty: 8 warp arrivals
        }
    }
    if (tid < BN)
        *(float*)(smem + OF_EXPA + tid * 4) = __expf(A_log[n0 + tid]);
    __syncthreads();

    // prologue: fill both stages (barriers fresh, no empty-wait needed)
    if (tid == 0) {
#pragma unroll
        for (int s = 0; s < NS; s++) {
            uint32_t stg = sb + s * STAGEB;
            uint32_t fb  = sb + OF_MBAR + s * 16;
            MBAR_EXPECT_TX(fb, (uint32_t)STAGEB);
            bulk_g2s(stg,             (const char*)g_Xt  + (size_t)(mb * NTILE + s) * TILEB, TILEB, fb);
            bulk_g2s(stg + TILEB,     (const char*)g_Wdt + (size_t)(nb * NTILE + s) * TILEB, TILEB, fb);
            bulk_g2s(stg + 2 * TILEB, (const char*)g_Wbt + (size_t)(nb * NTILE + s) * TILEB, TILEB, fb);
        }
    }

    float acc[2][4][4][4];               // [W][mi][ni][c] -> 128 regs
#pragma unroll
    for (int w = 0; w < 2; w++)
#pragma unroll
        for (int mi = 0; mi < 4; mi++)
#pragma unroll
            for (int ni = 0; ni < 4; ni++)
#pragma unroll
                for (int c = 0; c < 4; c++) acc[w][mi][ni][c] = 0.f;

    // Per-lane LDSM role offsets (within a stage), hoisted.
    int aOff[4], dOff[2], bOff[2];
#pragma unroll
    for (int mi = 0; mi < 4; mi++) {
        int r = wm * 64 + mi * 16 + (mid & 1) * 8 + l8;
        aOff[mi] = r * ROWB + (mid >> 1) * 16;
    }
#pragma unroll
    for (int p = 0; p < 2; p++) {
        int r = wn * 32 + (p * 2 + (mid >> 1)) * 8 + l8;
        int off = r * ROWB + (mid & 1) * 16;
        dOff[p] = TILEB + off;
        bOff[p] = 2 * TILEB + off;
    }

    const int lead = (lane == 0);        // one arrival per warp

    for (int i = 0; i < NTILE; i++) {
        const int s = i % NS;
        const uint32_t par = (uint32_t)((i / NS) & 1);
        const uint32_t fb = sb + OF_MBAR + s * 16;
        const uint32_t eb = fb + 8;

        mbar_wait(fb, par);              // stage s data ready

        const uint32_t sbase = sb + s * STAGEB;
        uint32_t aA[4], aD[2], aB2[2];
#pragma unroll
        for (int mi = 0; mi < 4; mi++) aA[mi] = sbase + aOff[mi];
#pragma unroll
        for (int p = 0; p < 2; p++) { aD[p] = sbase + dOff[p]; aB2[p] = sbase + bOff[p]; }

#pragma unroll
        for (int g = 0; g < 8; g++) {
            uint32_t af[4][4];
#pragma unroll
            for (int mi = 0; mi < 4; mi++)
                LDSM_X4(af[mi][0], af[mi][1], af[mi][2], af[mi][3], aA[mi] + g * 32);
            uint32_t wd[2][4], wb[2][4];
#pragma unroll
            for (int p = 0; p < 2; p++) {
                LDSM_X4(wd[p][0], wd[p][1], wd[p][2], wd[p][3], aD[p] + g * 32);
                LDSM_X4(wb[p][0], wb[p][1], wb[p][2], wb[p][3], aB2[p] + g * 32);
            }
#pragma unroll
            for (int ni = 0; ni < 4; ni++) {
                const int p  = ni >> 1;
                const int ix = (ni & 1) * 2;
                uint32_t bd0 = wd[p][ix], bd1 = wd[p][ix + 1];
                uint32_t bb0 = wb[p][ix], bb1 = wb[p][ix + 1];
#pragma unroll
                for (int mi = 0; mi < 4; mi++) {
                    mma_tf32(acc[0][mi][ni], af[mi], bd0, bd1);
                    mma_tf32(acc[1][mi][ni], af[mi], bb0, bb1);
                }
            }
        }

        // this warp is done reading stage s (ldmatrix is synchronous)
        if (lead) MBAR_ARRIVE(eb);

        // producer: refill stage s for tile j = i+NS once all warps released it
        const int j = i + NS;
        if (j < NTILE && tid == 0) {
            mbar_wait(eb, par);          // wait 8 warp arrivals of use i
            MBAR_EXPECT_TX(fb, (uint32_t)STAGEB);
            bulk_g2s(sbase,             (const char*)g_Xt  + (size_t)(mb * NTILE + j) * TILEB, TILEB, fb);
            bulk_g2s(sbase + TILEB,     (const char*)g_Wdt + (size_t)(nb * NTILE + j) * TILEB, TILEB, fb);
            bulk_g2s(sbase + 2 * TILEB, (const char*)g_Wbt + (size_t)(nb * NTILE + j) * TILEB, TILEB, fb);
        }
    }

    // -----------------------------------------------------------------------
    // Epilogue: fused softplus/exp -> write (At, Bt); simultaneously build the
    // 64-step chunk affine (P, Q) per column via shfl scans (fused pass1).
    // softplus uses the fast MUFU path: log(1+e), arg in (1,2].
    // -----------------------------------------------------------------------
    const float* sExpA = (const float*)(smem + OF_EXPA);
    const unsigned FULL = 0xffffffffu;
    float Pc[8], Qc[8];                  // per-column chunk affine (col = ni*2+c)
#pragma unroll
    for (int c = 0; c < 8; c++) { Pc[c] = 1.f; Qc[c] = 0.f; }

#pragma unroll
    for (int mi = 0; mi < 4; mi++) {
#pragma unroll
        for (int half = 0; half < 2; half++) {
#pragma unroll
            for (int ni = 0; ni < 4; ni++) {
                int colLoc = wn * 32 + ni * 8 + 2 * tig;
                float ea0 = sExpA[colLoc];
                float ea1 = sExpA[colLoc + 1];
                int row = m0 + wm * 64 + mi * 16 + half * 8 + grp;
                float zd0 = acc[0][mi][ni][half * 2 + 0];
                float zd1 = acc[0][mi][ni][half * 2 + 1];
                float zb0 = acc[1][mi][ni][half * 2 + 0];
                float zb1 = acc[1][mi][ni][half * 2 + 1];
                float d0 = fmaxf(zd0, 0.f) + __logf(1.f + __expf(-fabsf(zd0)));
                float d1 = fmaxf(zd1, 0.f) + __logf(1.f + __expf(-fabsf(zd1)));
                float a0 = __expf(-d0 * ea0);
                float a1 = __expf(-d1 * ea1);
                float b0 = d0 * zb0;
                float b1 = d1 * zb1;
                *(float4*)(&g_AB[(size_t)row * HH + (n0 + colLoc)]) =
                    make_float4(a0, b0, a1, b1);

                // segment scan over grp for the two columns
                float P0 = a0, Q0 = b0, P1 = a1, Q1 = b1;
#pragma unroll
                for (int d = 1; d < 8; d <<= 1) {
                    float Pi0 = __shfl_up_sync(FULL, P0, 4 * d);
                    float Qi0 = __shfl_up_sync(FULL, Q0, 4 * d);
                    float Pi1 = __shfl_up_sync(FULL, P1, 4 * d);
                    float Qi1 = __shfl_up_sync(FULL, Q1, 4 * d);
                    if (grp >= d) {
                        Q0 = fmaf(P0, Qi0, Q0); P0 *= Pi0;
                        Q1 = fmaf(P1, Qi1, Q1); P1 *= Pi1;
                    }
                }
                float Ps0 = __shfl_sync(FULL, P0, tig + 28);
                float Qs0 = __shfl_sync(FULL, Q0, tig + 28);
                float Ps1 = __shfl_sync(FULL, P1, tig + 28);
                float Qs1 = __shfl_sync(FULL, Q1, tig + 28);
                int col = ni * 2;
                Qc[col]     = fmaf(Ps0, Qc[col],     Qs0); Pc[col]     *= Ps0;
                Qc[col + 1] = fmaf(Ps1, Qc[col + 1], Qs1); Pc[col + 1] *= Ps1;
            }
        }
    }

    // grp==0 lanes write the chunk summaries (8 columns per writing lane)
    if (grp == 0) {
        int bglob  = m0 / TT;                              // batch
        int cchunk = ((m0 % TT) >> 6) + wm;                // chunk within batch
        int bc     = bglob * CHK + cchunk;
#pragma unroll
        for (int col = 0; col < 8; col++) {
            int h = n0 + wn * 32 + (col >> 1) * 8 + 2 * tig + (col & 1);
            g_PQ[(size_t)bc * HH + h] = make_float2(Pc[col], Qc[col]);
        }
    }

    __syncthreads();
    if (tid == 0) {
#pragma unroll
        for (int s = 0; s < NS; s++) {
            MBAR_INVAL(sb + OF_MBAR + s * 16);
            MBAR_INVAL(sb + OF_MBAR + s * 16 + 8);
        }
    }
}

// ---------------------------------------------------------------------------
// Scan pass 3 (pass2 fused): compute this chunk's start state by folding the
// prior chunk summaries (uniform c per block, 4-way load batching), then
// replay the chunk with fused tanh and write out.
// ---------------------------------------------------------------------------
__global__ void __launch_bounds__(256)
scan_pass3(float* __restrict__ out)
{
    const int idx = blockIdx.x * blockDim.x + threadIdx.x;
    const int h   = idx & (HH - 1);
    const int bc  = idx >> 10;
    const int c   = bc & (CHK - 1);      // uniform within the block
    const int b   = bc >> 5;

    // h0 = fold of chunk summaries 0..c-1 for this (b, h)
    const float2* __restrict__ pqb = g_PQ + (size_t)b * CHK * HH + h;
    float hs = 0.f;
    {
        int cc = 0;
        for (; cc + 4 <= c; cc += 4) {
            float2 v0 = pqb[(size_t)(cc + 0) * HH];
            float2 v1 = pqb[(size_t)(cc + 1) * HH];
            float2 v2 = pqb[(size_t)(cc + 2) * HH];
            float2 v3 = pqb[(size_t)(cc + 3) * HH];
            hs = fmaf(v0.x, hs, v0.y);
            hs = fmaf(v1.x, hs, v1.y);
            hs = fmaf(v2.x, hs, v2.y);
            hs = fmaf(v3.x, hs, v3.y);
        }
        for (; cc < c; cc++) {
            float2 v = pqb[(size_t)cc * HH];
            hs = fmaf(v.x, hs, v.y);
        }
    }

    const float2* __restrict__ p = g_AB + ((size_t)b * TT + (size_t)c * CL) * HH + h;
    float* __restrict__ o        = out  + ((size_t)b * TT + (size_t)c * CL) * HH + h;

    const int U = 8;
    float2 cur[U], nxt[U];
#pragma unroll
    for (int i = 0; i < U; i++) cur[i] = p[(size_t)i * HH];

    for (int t0 = 0; t0 < CL; t0 += U) {
        int tn = t0 + U;
        if (tn < CL) {
#pragma unroll
            for (int i = 0; i < U; i++) nxt[i] = p[(size_t)(tn + i) * HH];
        }
#pragma unroll
        for (int i = 0; i < U; i++) {
            hs = fmaf(cur[i].x, hs, cur[i].y);
            float e  = __expf(-2.f * fabsf(hs));
            float th = __fdividef(1.f - e, 1.f + e);
            o[(size_t)(t0 + i) * HH] = copysignf(th, hs);
        }
#pragma unroll
        for (int i = 0; i < U; i++) cur[i] = nxt[i];
    }
}

// ---------------------------------------------------------------------------
extern "C" void kernel_launch(void* const* d_in, const int* in_sizes, int n_in,
                              void* d_out, int out_size)
{
    const float* x     = (const float*)d_in[0];
    const float* Wd    = (const float*)d_in[1];
    const float* Wb    = (const float*)d_in[2];
    const float* A_log = (const float*)d_in[3];
    float* out         = (float*)d_out;

    // fused tf32-round + tile pre-pass (MLP-4 per thread)
    {
        int nt = NTX + 2 * NTW;
        prep_kernel<<<(nt + 255) / 256, 256>>>(x, Wd, Wb);
    }

    cudaFuncSetAttribute(gemm_mma_kernel,
                         cudaFuncAttributeMaxDynamicSharedMemorySize, SMEM_TOTAL);
    dim3 grid(HH / BN, MM / BM);       // (8, 128) = 1024 CTAs
    gemm_mma_kernel<<<grid, NTHR, SMEM_TOTAL>>>(A_log);

    scan_pass3<<<(BB * CHK * HH) / 256, 256>>>(out);
}

// round 16
// speedup vs baseline: 1.4236x; 1.0842x over previous
#include <cuda_runtime.h>
#include <cuda_fp16.h>
#include <cstdint>

// ---------------------------------------------------------------------------
// Problem constants
// ---------------------------------------------------------------------------
#define BB   8
#define TT   2048
#define IND  1024
#define HH   1024
#define MM   (BB * TT)          // 16384

// GEMM tiling
#define BM 128
#define BN 128
#define BK 64
#define NTILE (IND / BK)        // 16
#define NS 2                    // pipeline stages
#define NTHR 256                // 8 warps: 2(m) x 4(n), warp tile 64x32 per W

// Tile layout: 128 rows x 272 B (256 B data + 16 B pad -> conflict-free LDSM)
#define ROWB   272
#define TILEB  (128 * ROWB)     // 34816
#define STAGEB (3 * TILEB)      // A + Wd + Wb = 104448
#define OF_MBAR (NS * STAGEB)   // full[s] at +s*16, empty[s] at +s*16+8
#define OF_EXPA (OF_MBAR + 64)
#define SMEM_TOTAL (OF_EXPA + BN * 4 + 64)

// Scan chunking
#define CHK 32
#define CL  (TT / CHK)          // 64  (== wm half-tile height)

// ---------------------------------------------------------------------------
// Device scratch
// ---------------------------------------------------------------------------
__device__ float   g_Xt [(size_t)(MM / 128) * NTILE * (TILEB / 4)];  // ~71 MB
__device__ float   g_Wdt[(size_t)(HH / 128) * NTILE * (TILEB / 4)];
__device__ float   g_Wbt[(size_t)(HH / 128) * NTILE * (TILEB / 4)];
__device__ __half2 g_AB [(size_t)MM * HH];       // (At, Bt) as half2, 67 MB
__device__ float2  g_PQ [(size_t)BB * CHK * HH]; // chunk affine summaries

// ---------------------------------------------------------------------------
// helpers
// ---------------------------------------------------------------------------
__device__ __forceinline__ uint32_t smem_u32(const void* p) {
    uint32_t a;
    asm("{ .reg .u64 t; cvta.to.shared.u64 t, %1; cvt.u32.u64 %0, t; }" : "=r"(a) : "l"(p));
    return a;
}

__device__ __forceinline__ float tf32_round(float f) {
    uint32_t r;
    asm("cvt.rna.tf32.f32 %0, %1;" : "=r"(r) : "f"(f));
    return __uint_as_float(r);
}

__device__ __forceinline__ void mma_tf32(float* c, const uint32_t* a,
                                         uint32_t b0, uint32_t b1) {
    asm volatile(
        "mma.sync.aligned.m16n8k8.row.col.f32.tf32.tf32.f32 "
        "{%0,%1,%2,%3}, {%4,%5,%6,%7}, {%8,%9}, {%0,%1,%2,%3};"
        : "+f"(c[0]), "+f"(c[1]), "+f"(c[2]), "+f"(c[3])
        : "r"(a[0]), "r"(a[1]), "r"(a[2]), "r"(a[3]), "r"(b0), "r"(b1));
}

#define LDSM_X4(r0, r1, r2, r3, addr) \
    asm volatile("ldmatrix.sync.aligned.m8n8.x4.shared.b16 {%0,%1,%2,%3}, [%4];" \
                 : "=r"(r0), "=r"(r1), "=r"(r2), "=r"(r3) : "r"(addr))

#define MBAR_INIT(a, c) \
    asm volatile("mbarrier.init.shared.b64 [%0], %1;" :: "r"(a), "r"(c) : "memory")
#define MBAR_EXPECT_TX(a, b) \
    asm volatile("mbarrier.arrive.expect_tx.shared.b64 _, [%0], %1;" \
                 :: "r"(a), "r"(b) : "memory")
#define MBAR_ARRIVE(a) \
    asm volatile("mbarrier.arrive.shared.b64 _, [%0];" :: "r"(a) : "memory")
#define MBAR_INVAL(a) \
    asm volatile("mbarrier.inval.shared.b64 [%0];" :: "r"(a) : "memory")

__device__ __forceinline__ void bulk_g2s(uint32_t dst, const void* src,
                                         uint32_t bytes, uint32_t mbar) {
    asm volatile(
        "cp.async.bulk.shared::cluster.global.mbarrier::complete_tx::bytes "
        "[%0], [%1], %2, [%3];"
        :: "r"(dst), "l"(src), "r"(bytes), "r"(mbar) : "memory");
}

__device__ __forceinline__ void mbar_wait(uint32_t mbar, uint32_t parity) {
    asm volatile(
        "{\n\t.reg .pred P1;\n\t"
        "WAIT_LOOP_%=:\n\t"
        "mbarrier.try_wait.parity.acquire.cta.shared::cta.b64 P1, [%0], %1, 0x989680;\n\t"
        "@P1 bra.uni WAIT_DONE_%=;\n\t"
        "bra.uni WAIT_LOOP_%=;\n\t"
        "WAIT_DONE_%=:\n\t}"
        :: "r"(mbar), "r"(parity) : "memory");
}

// ---------------------------------------------------------------------------
// Kernel 0: fused tf32-round + tile copy for x, Wd, Wb (272B row stride).
// EXACT R13 structure (measured 28.6us): thread t -> (row, kt, g of 8).
// ---------------------------------------------------------------------------
#define NTX (MM * 128)
#define NTW (HH * 128)

__global__ void __launch_bounds__(256)
prep_kernel(const float* __restrict__ x, const float* __restrict__ Wd,
            const float* __restrict__ Wb)
{
    int t = blockIdx.x * blockDim.x + threadIdx.x;
    const float* src;
    float* dst;
    if (t < NTX) {
        src = x; dst = g_Xt;
    } else if (t < NTX + NTW) {
        t -= NTX; src = Wd; dst = g_Wdt;
    } else if (t < NTX + 2 * NTW) {
        t -= NTX + NTW; src = Wb; dst = g_Wbt;
    } else return;

    int g   = t & 7;
    int kt  = (t >> 3) & (NTILE - 1);
    int row = t >> 7;
    int blk = row >> 7;
    int r   = row & 127;

    const float4* s = (const float4*)(src + (size_t)row * IND + kt * BK + g * 8);
    float4 lo = s[0], hi = s[1];
    lo.x = tf32_round(lo.x); lo.y = tf32_round(lo.y);
    lo.z = tf32_round(lo.z); lo.w = tf32_round(lo.w);
    hi.x = tf32_round(hi.x); hi.y = tf32_round(hi.y);
    hi.z = tf32_round(hi.z); hi.w = tf32_round(hi.w);

    size_t dstb = (size_t)(blk * NTILE + kt) * TILEB + (size_t)r * ROWB + g * 32;
    float4* d = (float4*)((char*)dst + dstb);
    d[0] = lo; d[1] = hi;
}

// ---------------------------------------------------------------------------
// Kernel 1: TF32 mma.sync dual GEMM via ldmatrix, cp.async.bulk 2-stage
// full/empty mbarrier pipeline, fused activation + chunk-affine (pass1)
// epilogue. 256 threads = 8 warps in 2(m) x 4(n); warp tile 64x32 per W.
// Epilogue stores (At,Bt) as half2 (P/Q scan uses the fp16-rounded values so
// pass3's h0 fold is consistent with its replay).
// ---------------------------------------------------------------------------
__global__ void __launch_bounds__(NTHR, 1)
gemm_mma_kernel(const float* __restrict__ A_log)
{
    extern __shared__ __align__(128) char smem[];
    const uint32_t sb = smem_u32(smem);
    const int tid  = threadIdx.x;
    const int warp = tid >> 5;
    const int lane = tid & 31;
    const int wm   = warp >> 2;          // 0..1
    const int wn   = warp & 3;           // 0..3
    const int grp  = lane >> 2;          // 0..7
    const int tig  = lane & 3;           // 0..3
    const int mid  = lane >> 3;          // matrix id 0..3 within LDSM.x4
    const int l8   = lane & 7;           // row within matrix
    const int n0   = blockIdx.x * BN;
    const int m0   = blockIdx.y * BM;
    const int mb   = blockIdx.y;
    const int nb   = blockIdx.x;

    if (tid == 0) {
#pragma unroll
        for (int s = 0; s < NS; s++) {
            MBAR_INIT(sb + OF_MBAR + s * 16, 1);       // full: tx-based
            MBAR_INIT(sb + OF_MBAR + s * 16 + 8, 8);   // empty: 8 warp arrivals
        }
    }
    if (tid < BN)
        *(float*)(smem + OF_EXPA + tid * 4) = __expf(A_log[n0 + tid]);
    __syncthreads();

    // prologue: fill both stages (barriers fresh, no empty-wait needed)
    if (tid == 0) {
#pragma unroll
        for (int s = 0; s < NS; s++) {
            uint32_t stg = sb + s * STAGEB;
            uint32_t fb  = sb + OF_MBAR + s * 16;
            MBAR_EXPECT_TX(fb, (uint32_t)STAGEB);
            bulk_g2s(stg,             (const char*)g_Xt  + (size_t)(mb * NTILE + s) * TILEB, TILEB, fb);
            bulk_g2s(stg + TILEB,     (const char*)g_Wdt + (size_t)(nb * NTILE + s) * TILEB, TILEB, fb);
            bulk_g2s(stg + 2 * TILEB, (const char*)g_Wbt + (size_t)(nb * NTILE + s) * TILEB, TILEB, fb);
        }
    }

    float acc[2][4][4][4];               // [W][mi][ni][c] -> 128 regs
#pragma unroll
    for (int w = 0; w < 2; w++)
#pragma unroll
        for (int mi = 0; mi < 4; mi++)
#pragma unroll
            for (int ni = 0; ni < 4; ni++)
#pragma unroll
                for (int c = 0; c < 4; c++) acc[w][mi][ni][c] = 0.f;

    // Per-lane LDSM role offsets (within a stage), hoisted.
    int aOff[4], dOff[2], bOff[2];
#pragma unroll
    for (int mi = 0; mi < 4; mi++) {
        int r = wm * 64 + mi * 16 + (mid & 1) * 8 + l8;
        aOff[mi] = r * ROWB + (mid >> 1) * 16;
    }
#pragma unroll
    for (int p = 0; p < 2; p++) {
        int r = wn * 32 + (p * 2 + (mid >> 1)) * 8 + l8;
        int off = r * ROWB + (mid & 1) * 16;
        dOff[p] = TILEB + off;
        bOff[p] = 2 * TILEB + off;
    }

    const int lead = (lane == 0);        // one arrival per warp

    for (int i = 0; i < NTILE; i++) {
        const int s = i % NS;
        const uint32_t par = (uint32_t)((i / NS) & 1);
        const uint32_t fb = sb + OF_MBAR + s * 16;
        const uint32_t eb = fb + 8;

        mbar_wait(fb, par);              // stage s data ready

        const uint32_t sbase = sb + s * STAGEB;
        uint32_t aA[4], aD[2], aB2[2];
#pragma unroll
        for (int mi = 0; mi < 4; mi++) aA[mi] = sbase + aOff[mi];
#pragma unroll
        for (int p = 0; p < 2; p++) { aD[p] = sbase + dOff[p]; aB2[p] = sbase + bOff[p]; }

#pragma unroll
        for (int g = 0; g < 8; g++) {
            uint32_t af[4][4];
#pragma unroll
            for (int mi = 0; mi < 4; mi++)
                LDSM_X4(af[mi][0], af[mi][1], af[mi][2], af[mi][3], aA[mi] + g * 32);
            uint32_t wd[2][4], wb[2][4];
#pragma unroll
            for (int p = 0; p < 2; p++) {
                LDSM_X4(wd[p][0], wd[p][1], wd[p][2], wd[p][3], aD[p] + g * 32);
                LDSM_X4(wb[p][0], wb[p][1], wb[p][2], wb[p][3], aB2[p] + g * 32);
            }
#pragma unroll
            for (int ni = 0; ni < 4; ni++) {
                const int p  = ni >> 1;
                const int ix = (ni & 1) * 2;
                uint32_t bd0 = wd[p][ix], bd1 = wd[p][ix + 1];
                uint32_t bb0 = wb[p][ix], bb1 = wb[p][ix + 1];
#pragma unroll
                for (int mi = 0; mi < 4; mi++) {
                    mma_tf32(acc[0][mi][ni], af[mi], bd0, bd1);
                    mma_tf32(acc[1][mi][ni], af[mi], bb0, bb1);
                }
            }
        }

        // this warp is done reading stage s (ldmatrix is synchronous)
        if (lead) MBAR_ARRIVE(eb);

        // producer: refill stage s for tile j = i+NS once all warps released it
        const int j = i + NS;
        if (j < NTILE && tid == 0) {
            mbar_wait(eb, par);          // wait 8 warp arrivals of use i
            MBAR_EXPECT_TX(fb, (uint32_t)STAGEB);
            bulk_g2s(sbase,             (const char*)g_Xt  + (size_t)(mb * NTILE + j) * TILEB, TILEB, fb);
            bulk_g2s(sbase + TILEB,     (const char*)g_Wdt + (size_t)(nb * NTILE + j) * TILEB, TILEB, fb);
            bulk_g2s(sbase + 2 * TILEB, (const char*)g_Wbt + (size_t)(nb * NTILE + j) * TILEB, TILEB, fb);
        }
    }

    // -----------------------------------------------------------------------
    // Epilogue: fused softplus/exp -> write (At, Bt) as half2; chunk affine
    // (P, Q) via shfl scans from the fp16-rounded values.
    // -----------------------------------------------------------------------
    const float* sExpA = (const float*)(smem + OF_EXPA);
    const unsigned FULL = 0xffffffffu;
    float Pc[8], Qc[8];                  // per-column chunk affine (col = ni*2+c)
#pragma unroll
    for (int c = 0; c < 8; c++) { Pc[c] = 1.f; Qc[c] = 0.f; }

#pragma unroll
    for (int mi = 0; mi < 4; mi++) {
#pragma unroll
        for (int half = 0; half < 2; half++) {
#pragma unroll
            for (int ni = 0; ni < 4; ni++) {
                int colLoc = wn * 32 + ni * 8 + 2 * tig;
                float ea0 = sExpA[colLoc];
                float ea1 = sExpA[colLoc + 1];
                int row = m0 + wm * 64 + mi * 16 + half * 8 + grp;
                float zd0 = acc[0][mi][ni][half * 2 + 0];
                float zd1 = acc[0][mi][ni][half * 2 + 1];
                float zb0 = acc[1][mi][ni][half * 2 + 0];
                float zb1 = acc[1][mi][ni][half * 2 + 1];
                float d0 = fmaxf(zd0, 0.f) + __logf(1.f + __expf(-fabsf(zd0)));
                float d1 = fmaxf(zd1, 0.f) + __logf(1.f + __expf(-fabsf(zd1)));
                float a0 = __expf(-d0 * ea0);
                float a1 = __expf(-d1 * ea1);
                float b0 = d0 * zb0;
                float b1 = d1 * zb1;

                // fp16 round, store, and use the ROUNDED values for the scan
                __half2 h0 = __floats2half2_rn(a0, b0);
                __half2 h1 = __floats2half2_rn(a1, b1);
                *(uint2*)(&g_AB[(size_t)row * HH + (n0 + colLoc)]) =
                    make_uint2(*(uint32_t*)&h0, *(uint32_t*)&h1);
                a0 = __low2float(h0);  b0 = __high2float(h0);
                a1 = __low2float(h1);  b1 = __high2float(h1);

                // segment scan over grp for the two columns
                float P0 = a0, Q0 = b0, P1 = a1, Q1 = b1;
#pragma unroll
                for (int d = 1; d < 8; d <<= 1) {
                    float Pi0 = __shfl_up_sync(FULL, P0, 4 * d);
                    float Qi0 = __shfl_up_sync(FULL, Q0, 4 * d);
                    float Pi1 = __shfl_up_sync(FULL, P1, 4 * d);
                    float Qi1 = __shfl_up_sync(FULL, Q1, 4 * d);
                    if (grp >= d) {
                        Q0 = fmaf(P0, Qi0, Q0); P0 *= Pi0;
                        Q1 = fmaf(P1, Qi1, Q1); P1 *= Pi1;
                    }
                }
                float Ps0 = __shfl_sync(FULL, P0, tig + 28);
                float Qs0 = __shfl_sync(FULL, Q0, tig + 28);
                float Ps1 = __shfl_sync(FULL, P1, tig + 28);
                float Qs1 = __shfl_sync(FULL, Q1, tig + 28);
                int col = ni * 2;
                Qc[col]     = fmaf(Ps0, Qc[col],     Qs0); Pc[col]     *= Ps0;
                Qc[col + 1] = fmaf(Ps1, Qc[col + 1], Qs1); Pc[col + 1] *= Ps1;
            }
        }
    }

    // grp==0 lanes write the chunk summaries (8 columns per writing lane)
    if (grp == 0) {
        int bglob  = m0 / TT;                              // batch
        int cchunk = ((m0 % TT) >> 6) + wm;                // chunk within batch
        int bc     = bglob * CHK + cchunk;
#pragma unroll
        for (int col = 0; col < 8; col++) {
            int h = n0 + wn * 32 + (col >> 1) * 8 + 2 * tig + (col & 1);
            g_PQ[(size_t)bc * HH + h] = make_float2(Pc[col], Qc[col]);
        }
    }

    __syncthreads();
    if (tid == 0) {
#pragma unroll
        for (int s = 0; s < NS; s++) {
            MBAR_INVAL(sb + OF_MBAR + s * 16);
            MBAR_INVAL(sb + OF_MBAR + s * 16 + 8);
        }
    }
}

// ---------------------------------------------------------------------------
// Scan pass 3 (pass2 fused): fold prior chunk summaries -> h0, then replay
// the chunk from half2 (a,b) with fused tanh, write fp32 out. U=16 prefetch
// (4 B loads need deeper MLP to stay bandwidth-bound).
// ---------------------------------------------------------------------------
__global__ void __launch_bounds__(256)
scan_pass3(float* __restrict__ out)
{
    const int idx = blockIdx.x * blockDim.x + threadIdx.x;
    const int h   = idx & (HH - 1);
    const int bc  = idx >> 10;
    const int c   = bc & (CHK - 1);      // uniform within the block
    const int b   = bc >> 5;

    // h0 = fold of chunk summaries 0..c-1 for this (b, h)
    const float2* __restrict__ pqb = g_PQ + (size_t)b * CHK * HH + h;
    float hs = 0.f;
    {
        int cc = 0;
        for (; cc + 4 <= c; cc += 4) {
            float2 v0 = pqb[(size_t)(cc + 0) * HH];
            float2 v1 = pqb[(size_t)(cc + 1) * HH];
            float2 v2 = pqb[(size_t)(cc + 2) * HH];
            float2 v3 = pqb[(size_t)(cc + 3) * HH];
            hs = fmaf(v0.x, hs, v0.y);
            hs = fmaf(v1.x, hs, v1.y);
            hs = fmaf(v2.x, hs, v2.y);
            hs = fmaf(v3.x, hs, v3.y);
        }
        for (; cc < c; cc++) {
            float2 v = pqb[(size_t)cc * HH];
            hs = fmaf(v.x, hs, v.y);
        }
    }

    const __half2* __restrict__ p = g_AB + ((size_t)b * TT + (size_t)c * CL) * HH + h;
    float* __restrict__ o         = out  + ((size_t)b * TT + (size_t)c * CL) * HH + h;

    const int U = 16;
    __half2 cur[U], nxt[U];
#pragma unroll
    for (int i = 0; i < U; i++) cur[i] = p[(size_t)i * HH];

    for (int t0 = 0; t0 < CL; t0 += U) {
        int tn = t0 + U;
        if (tn < CL) {
#pragma unroll
            for (int i = 0; i < U; i++) nxt[i] = p[(size_t)(tn + i) * HH];
        }
#pragma unroll
        for (int i = 0; i < U; i++) {
            float a = __low2float(cur[i]);
            float bq = __high2float(cur[i]);
            hs = fmaf(a, hs, bq);
            float e  = __expf(-2.f * fabsf(hs));
            float th = __fdividef(1.f - e, 1.f + e);
            o[(size_t)(t0 + i) * HH] = copysignf(th, hs);
        }
#pragma unroll
        for (int i = 0; i < U; i++) cur[i] = nxt[i];
    }
}

// ---------------------------------------------------------------------------
extern "C" void kernel_launch(void* const* d_in, const int* in_sizes, int n_in,
                              void* d_out, int out_size)
{
    const float* x     = (const float*)d_in[0];
    const float* Wd    = (const float*)d_in[1];
    const float* Wb    = (const float*)d_in[2];
    const float* A_log = (const float*)d_in[3];
    float* out         = (float*)d_out;

    // fused tf32-round + tile pre-pass (exact R13 structure)
    {
        int nt = NTX + 2 * NTW;
        prep_kernel<<<(nt + 255) / 256, 256>>>(x, Wd, Wb);
    }

    cudaFuncSetAttribute(gemm_mma_kernel,
                         cudaFuncAttributeMaxDynamicSharedMemorySize, SMEM_TOTAL);
    dim3 grid(HH / BN, MM / BM);       // (8, 128) = 1024 CTAs
    gemm_mma_kernel<<<grid, NTHR, SMEM_TOTAL>>>(A_log);

    scan_pass3<<<(BB * CHK * HH) / 256, 256>>>(out);
}

// round 17
// speedup vs baseline: 1.4278x; 1.0030x over previous
#include <cuda_runtime.h>
#include <cuda_fp16.h>
#include <cstdint>

// ---------------------------------------------------------------------------
// Problem constants
// ---------------------------------------------------------------------------
#define BB   8
#define TT   2048
#define IND  1024
#define HH   1024
#define MM   (BB * TT)          // 16384

// GEMM tiling
#define BM 128
#define BN 128
#define BK 64
#define NTILE (IND / BK)        // 16
#define NS 2                    // pipeline stages
#define NTHR 256                // 8 warps: 2(m) x 4(n), warp tile 64x32 per W

// Tile layout: 128 rows x 272 B (256 B data + 16 B pad -> conflict-free LDSM)
#define ROWB   272
#define TILEB  (128 * ROWB)     // 34816
#define STAGEB (3 * TILEB)      // A + Wd + Wb = 104448
#define OF_MBAR (NS * STAGEB)   // full[s] at +s*16, empty[s] at +s*16+8
#define OF_EXPA (OF_MBAR + 64)
#define SMEM_TOTAL (OF_EXPA + BN * 4 + 64)

// Scan chunking
#define CHK 32
#define CL  (TT / CHK)          // 64  (== wm half-tile height)

// ---------------------------------------------------------------------------
// Device scratch
// ---------------------------------------------------------------------------
__device__ float   g_Xt [(size_t)(MM / 128) * NTILE * (TILEB / 4)];  // ~71 MB
__device__ float   g_Wdt[(size_t)(HH / 128) * NTILE * (TILEB / 4)];
__device__ float   g_Wbt[(size_t)(HH / 128) * NTILE * (TILEB / 4)];
__device__ __half2 g_AB [(size_t)MM * HH];       // (At, Bt) as half2, 67 MB
__device__ float2  g_PQ [(size_t)BB * CHK * HH]; // chunk affine summaries

// ---------------------------------------------------------------------------
// helpers
// ---------------------------------------------------------------------------
__device__ __forceinline__ uint32_t smem_u32(const void* p) {
    uint32_t a;
    asm("{ .reg .u64 t; cvta.to.shared.u64 t, %1; cvt.u32.u64 %0, t; }" : "=r"(a) : "l"(p));
    return a;
}

__device__ __forceinline__ float tf32_round(float f) {
    uint32_t r;
    asm("cvt.rna.tf32.f32 %0, %1;" : "=r"(r) : "f"(f));
    return __uint_as_float(r);
}

__device__ __forceinline__ void mma_tf32(float* c, const uint32_t* a,
                                         uint32_t b0, uint32_t b1) {
    asm volatile(
        "mma.sync.aligned.m16n8k8.row.col.f32.tf32.tf32.f32 "
        "{%0,%1,%2,%3}, {%4,%5,%6,%7}, {%8,%9}, {%0,%1,%2,%3};"
        : "+f"(c[0]), "+f"(c[1]), "+f"(c[2]), "+f"(c[3])
        : "r"(a[0]), "r"(a[1]), "r"(a[2]), "r"(a[3]), "r"(b0), "r"(b1));
}

#define LDSM_X4(r0, r1, r2, r3, addr) \
    asm volatile("ldmatrix.sync.aligned.m8n8.x4.shared.b16 {%0,%1,%2,%3}, [%4];" \
                 : "=r"(r0), "=r"(r1), "=r"(r2), "=r"(r3) : "r"(addr))

#define MBAR_INIT(a, c) \
    asm volatile("mbarrier.init.shared.b64 [%0], %1;" :: "r"(a), "r"(c) : "memory")
#define MBAR_EXPECT_TX(a, b) \
    asm volatile("mbarrier.arrive.expect_tx.shared.b64 _, [%0], %1;" \
                 :: "r"(a), "r"(b) : "memory")
#define MBAR_ARRIVE(a) \
    asm volatile("mbarrier.arrive.shared.b64 _, [%0];" :: "r"(a) : "memory")
#define MBAR_INVAL(a) \
    asm volatile("mbarrier.inval.shared.b64 [%0];" :: "r"(a) : "memory")

__device__ __forceinline__ void bulk_g2s(uint32_t dst, const void* src,
                                         uint32_t bytes, uint32_t mbar) {
    asm volatile(
        "cp.async.bulk.shared::cluster.global.mbarrier::complete_tx::bytes "
        "[%0], [%1], %2, [%3];"
        :: "r"(dst), "l"(src), "r"(bytes), "r"(mbar) : "memory");
}

__device__ __forceinline__ void mbar_wait(uint32_t mbar, uint32_t parity) {
    asm volatile(
        "{\n\t.reg .pred P1;\n\t"
        "WAIT_LOOP_%=:\n\t"
        "mbarrier.try_wait.parity.acquire.cta.shared::cta.b64 P1, [%0], %1, 0x989680;\n\t"
        "@P1 bra.uni WAIT_DONE_%=;\n\t"
        "bra.uni WAIT_LOOP_%=;\n\t"
        "WAIT_DONE_%=:\n\t}"
        :: "r"(mbar), "r"(parity) : "memory");
}

// ---------------------------------------------------------------------------
// Kernel 0: fused tf32-round + tile copy for x, Wd, Wb (272B row stride).
// EXACT R13 structure (measured 28.6us): thread t -> (row, kt, g of 8).
// ---------------------------------------------------------------------------
#define NTX (MM * 128)
#define NTW (HH * 128)

__global__ void __launch_bounds__(256)
prep_kernel(const float* __restrict__ x, const float* __restrict__ Wd,
            const float* __restrict__ Wb)
{
    int t = blockIdx.x * blockDim.x + threadIdx.x;
    const float* src;
    float* dst;
    if (t < NTX) {
        src = x; dst = g_Xt;
    } else if (t < NTX + NTW) {
        t -= NTX; src = Wd; dst = g_Wdt;
    } else if (t < NTX + 2 * NTW) {
        t -= NTX + NTW; src = Wb; dst = g_Wbt;
    } else return;

    int g   = t & 7;
    int kt  = (t >> 3) & (NTILE - 1);
    int row = t >> 7;
    int blk = row >> 7;
    int r   = row & 127;

    const float4* s = (const float4*)(src + (size_t)row * IND + kt * BK + g * 8);
    float4 lo = s[0], hi = s[1];
    lo.x = tf32_round(lo.x); lo.y = tf32_round(lo.y);
    lo.z = tf32_round(lo.z); lo.w = tf32_round(lo.w);
    hi.x = tf32_round(hi.x); hi.y = tf32_round(hi.y);
    hi.z = tf32_round(hi.z); hi.w = tf32_round(hi.w);

    size_t dstb = (size_t)(blk * NTILE + kt) * TILEB + (size_t)r * ROWB + g * 32;
    float4* d = (float4*)((char*)dst + dstb);
    d[0] = lo; d[1] = hi;
}

// ---------------------------------------------------------------------------
// Kernel 1: TF32 mma.sync dual GEMM via ldmatrix, cp.async.bulk 2-stage
// full/empty mbarrier pipeline, fused activation + chunk-affine (pass1)
// epilogue. 256 threads = 8 warps in 2(m) x 4(n); warp tile 64x32 per W.
// Odd warps traverse k-groups phase-shifted by 4 (g ^= 4) so the two warps
// sharing an SMSP anti-align their LDSM phases (HMMA covers the other's loads).
// ---------------------------------------------------------------------------
__global__ void __launch_bounds__(NTHR, 1)
gemm_mma_kernel(const float* __restrict__ A_log)
{
    extern __shared__ __align__(128) char smem[];
    const uint32_t sb = smem_u32(smem);
    const int tid  = threadIdx.x;
    const int warp = tid >> 5;
    const int lane = tid & 31;
    const int wm   = warp >> 2;          // 0..1
    const int wn   = warp & 3;           // 0..3
    const int grp  = lane >> 2;          // 0..7
    const int tig  = lane & 3;           // 0..3
    const int mid  = lane >> 3;          // matrix id 0..3 within LDSM.x4
    const int l8   = lane & 7;           // row within matrix
    const int gxor = (warp & 1) << 2;    // per-warp k-group phase stagger
    const int n0   = blockIdx.x * BN;
    const int m0   = blockIdx.y * BM;
    const int mb   = blockIdx.y;
    const int nb   = blockIdx.x;

    if (tid == 0) {
#pragma unroll
        for (int s = 0; s < NS; s++) {
            MBAR_INIT(sb + OF_MBAR + s * 16, 1);       // full: tx-based
            MBAR_INIT(sb + OF_MBAR + s * 16 + 8, 8);   // empty: 8 warp arrivals
        }
    }
    if (tid < BN)
        *(float*)(smem + OF_EXPA + tid * 4) = __expf(A_log[n0 + tid]);
    __syncthreads();

    // prologue: fill both stages (barriers fresh, no empty-wait needed)
    if (tid == 0) {
#pragma unroll
        for (int s = 0; s < NS; s++) {
            uint32_t stg = sb + s * STAGEB;
            uint32_t fb  = sb + OF_MBAR + s * 16;
            MBAR_EXPECT_TX(fb, (uint32_t)STAGEB);
            bulk_g2s(stg,             (const char*)g_Xt  + (size_t)(mb * NTILE + s) * TILEB, TILEB, fb);
            bulk_g2s(stg + TILEB,     (const char*)g_Wdt + (size_t)(nb * NTILE + s) * TILEB, TILEB, fb);
            bulk_g2s(stg + 2 * TILEB, (const char*)g_Wbt + (size_t)(nb * NTILE + s) * TILEB, TILEB, fb);
        }
    }

    float acc[2][4][4][4];               // [W][mi][ni][c] -> 128 regs
#pragma unroll
    for (int w = 0; w < 2; w++)
#pragma unroll
        for (int mi = 0; mi < 4; mi++)
#pragma unroll
            for (int ni = 0; ni < 4; ni++)
#pragma unroll
                for (int c = 0; c < 4; c++) acc[w][mi][ni][c] = 0.f;

    // Per-lane LDSM role offsets (within a stage), hoisted.
    int aOff[4], dOff[2], bOff[2];
#pragma unroll
    for (int mi = 0; mi < 4; mi++) {
        int r = wm * 64 + mi * 16 + (mid & 1) * 8 + l8;
        aOff[mi] = r * ROWB + (mid >> 1) * 16;
    }
#pragma unroll
    for (int p = 0; p < 2; p++) {
        int r = wn * 32 + (p * 2 + (mid >> 1)) * 8 + l8;
        int off = r * ROWB + (mid & 1) * 16;
        dOff[p] = TILEB + off;
        bOff[p] = 2 * TILEB + off;
    }

    const int lead = (lane == 0);        // one arrival per warp

    for (int i = 0; i < NTILE; i++) {
        const int s = i % NS;
        const uint32_t par = (uint32_t)((i / NS) & 1);
        const uint32_t fb = sb + OF_MBAR + s * 16;
        const uint32_t eb = fb + 8;

        mbar_wait(fb, par);              // stage s data ready

        const uint32_t sbase = sb + s * STAGEB;
        uint32_t aA[4], aD[2], aB2[2];
#pragma unroll
        for (int mi = 0; mi < 4; mi++) aA[mi] = sbase + aOff[mi];
#pragma unroll
        for (int p = 0; p < 2; p++) { aD[p] = sbase + dOff[p]; aB2[p] = sbase + bOff[p]; }

#pragma unroll
        for (int gg = 0; gg < 8; gg++) {
            const int g = gg ^ gxor;     // phase-staggered k-group order
            uint32_t af[4][4];
#pragma unroll
            for (int mi = 0; mi < 4; mi++)
                LDSM_X4(af[mi][0], af[mi][1], af[mi][2], af[mi][3], aA[mi] + g * 32);
            uint32_t wd[2][4], wb[2][4];
#pragma unroll
            for (int p = 0; p < 2; p++) {
                LDSM_X4(wd[p][0], wd[p][1], wd[p][2], wd[p][3], aD[p] + g * 32);
                LDSM_X4(wb[p][0], wb[p][1], wb[p][2], wb[p][3], aB2[p] + g * 32);
            }
#pragma unroll
            for (int ni = 0; ni < 4; ni++) {
                const int p  = ni >> 1;
                const int ix = (ni & 1) * 2;
                uint32_t bd0 = wd[p][ix], bd1 = wd[p][ix + 1];
                uint32_t bb0 = wb[p][ix], bb1 = wb[p][ix + 1];
#pragma unroll
                for (int mi = 0; mi < 4; mi++) {
                    mma_tf32(acc[0][mi][ni], af[mi], bd0, bd1);
                    mma_tf32(acc[1][mi][ni], af[mi], bb0, bb1);
                }
            }
        }

        // this warp is done reading stage s (ldmatrix is synchronous)
        if (lead) MBAR_ARRIVE(eb);

        // producer: refill stage s for tile j = i+NS once all warps released it
        const int j = i + NS;
        if (j < NTILE && tid == 0) {
            mbar_wait(eb, par);          // wait 8 warp arrivals of use i
            MBAR_EXPECT_TX(fb, (uint32_t)STAGEB);
            bulk_g2s(sbase,             (const char*)g_Xt  + (size_t)(mb * NTILE + j) * TILEB, TILEB, fb);
            bulk_g2s(sbase + TILEB,     (const char*)g_Wdt + (size_t)(nb * NTILE + j) * TILEB, TILEB, fb);
            bulk_g2s(sbase + 2 * TILEB, (const char*)g_Wbt + (size_t)(nb * NTILE + j) * TILEB, TILEB, fb);
        }
    }

    // -----------------------------------------------------------------------
    // Epilogue: fused softplus/exp -> write (At, Bt) as half2; chunk affine
    // (P, Q) via shfl scans from the fp16-rounded values.
    // -----------------------------------------------------------------------
    const float* sExpA = (const float*)(smem + OF_EXPA);
    const unsigned FULL = 0xffffffffu;
    float Pc[8], Qc[8];                  // per-column chunk affine (col = ni*2+c)
#pragma unroll
    for (int c = 0; c < 8; c++) { Pc[c] = 1.f; Qc[c] = 0.f; }

#pragma unroll
    for (int mi = 0; mi < 4; mi++) {
#pragma unroll
        for (int half = 0; half < 2; half++) {
#pragma unroll
            for (int ni = 0; ni < 4; ni++) {
                int colLoc = wn * 32 + ni * 8 + 2 * tig;
                float ea0 = sExpA[colLoc];
                float ea1 = sExpA[colLoc + 1];
                int row = m0 + wm * 64 + mi * 16 + half * 8 + grp;
                float zd0 = acc[0][mi][ni][half * 2 + 0];
                float zd1 = acc[0][mi][ni][half * 2 + 1];
                float zb0 = acc[1][mi][ni][half * 2 + 0];
                float zb1 = acc[1][mi][ni][half * 2 + 1];
                float d0 = fmaxf(zd0, 0.f) + __logf(1.f + __expf(-fabsf(zd0)));
                float d1 = fmaxf(zd1, 0.f) + __logf(1.f + __expf(-fabsf(zd1)));
                float a0 = __expf(-d0 * ea0);
                float a1 = __expf(-d1 * ea1);
                float b0 = d0 * zb0;
                float b1 = d1 * zb1;

                // fp16 round, store, and use the ROUNDED values for the scan
                __half2 h0 = __floats2half2_rn(a0, b0);
                __half2 h1 = __floats2half2_rn(a1, b1);
                *(uint2*)(&g_AB[(size_t)row * HH + (n0 + colLoc)]) =
                    make_uint2(*(uint32_t*)&h0, *(uint32_t*)&h1);
                a0 = __low2float(h0);  b0 = __high2float(h0);
                a1 = __low2float(h1);  b1 = __high2float(h1);

                // segment scan over grp for the two columns
                float P0 = a0, Q0 = b0, P1 = a1, Q1 = b1;
#pragma unroll
                for (int d = 1; d < 8; d <<= 1) {
                    float Pi0 = __shfl_up_sync(FULL, P0, 4 * d);
                    float Qi0 = __shfl_up_sync(FULL, Q0, 4 * d);
                    float Pi1 = __shfl_up_sync(FULL, P1, 4 * d);
                    float Qi1 = __shfl_up_sync(FULL, Q1, 4 * d);
                    if (grp >= d) {
                        Q0 = fmaf(P0, Qi0, Q0); P0 *= Pi0;
                        Q1 = fmaf(P1, Qi1, Q1); P1 *= Pi1;
                    }
                }
                float Ps0 = __shfl_sync(FULL, P0, tig + 28);
                float Qs0 = __shfl_sync(FULL, Q0, tig + 28);
                float Ps1 = __shfl_sync(FULL, P1, tig + 28);
                float Qs1 = __shfl_sync(FULL, Q1, tig + 28);
                int col = ni * 2;
                Qc[col]     = fmaf(Ps0, Qc[col],     Qs0); Pc[col]     *= Ps0;
                Qc[col + 1] = fmaf(Ps1, Qc[col + 1], Qs1); Pc[col + 1] *= Ps1;
            }
        }
    }

    // grp==0 lanes write the chunk summaries (8 columns per writing lane)
    if (grp == 0) {
        int bglob  = m0 / TT;                              // batch
        int cchunk = ((m0 % TT) >> 6) + wm;                // chunk within batch
        int bc     = bglob * CHK + cchunk;
#pragma unroll
        for (int col = 0; col < 8; col++) {
            int h = n0 + wn * 32 + (col >> 1) * 8 + 2 * tig + (col & 1);
            g_PQ[(size_t)bc * HH + h] = make_float2(Pc[col], Qc[col]);
        }
    }

    __syncthreads();
    if (tid == 0) {
#pragma unroll
        for (int s = 0; s < NS; s++) {
            MBAR_INVAL(sb + OF_MBAR + s * 16);
            MBAR_INVAL(sb + OF_MBAR + s * 16 + 8);
        }
    }
}

// ---------------------------------------------------------------------------
// Scan pass 3 (pass2 fused): fold prior chunk summaries -> h0, then replay
// the chunk from half2 (a,b) with fused tanh, streaming-store fp32 out.
// ---------------------------------------------------------------------------
__global__ void __launch_bounds__(256)
scan_pass3(float* __restrict__ out)
{
    const int idx = blockIdx.x * blockDim.x + threadIdx.x;
    const int h   = idx & (HH - 1);
    const int bc  = idx >> 10;
    const int c   = bc & (CHK - 1);      // uniform within the block
    const int b   = bc >> 5;

    // h0 = fold of chunk summaries 0..c-1 for this (b, h)
    const float2* __restrict__ pqb = g_PQ + (size_t)b * CHK * HH + h;
    float hs = 0.f;
    {
        int cc = 0;
        for (; cc + 4 <= c; cc += 4) {
            float2 v0 = pqb[(size_t)(cc + 0) * HH];
            float2 v1 = pqb[(size_t)(cc + 1) * HH];
            float2 v2 = pqb[(size_t)(cc + 2) * HH];
            float2 v3 = pqb[(size_t)(cc + 3) * HH];
            hs = fmaf(v0.x, hs, v0.y);
            hs = fmaf(v1.x, hs, v1.y);
            hs = fmaf(v2.x, hs, v2.y);
            hs = fmaf(v3.x, hs, v3.y);
        }
        for (; cc < c; cc++) {
            float2 v = pqb[(size_t)cc * HH];
            hs = fmaf(v.x, hs, v.y);
        }
    }

    const __half2* __restrict__ p = g_AB + ((size_t)b * TT + (size_t)c * CL) * HH + h;
    float* __restrict__ o         = out  + ((size_t)b * TT + (size_t)c * CL) * HH + h;

    const int U = 16;
    __half2 cur[U], nxt[U];
#pragma unroll
    for (int i = 0; i < U; i++) cur[i] = p[(size_t)i * HH];

    for (int t0 = 0; t0 < CL; t0 += U) {
        int tn = t0 + U;
        if (tn < CL) {
#pragma unroll
            for (int i = 0; i < U; i++) nxt[i] = p[(size_t)(tn + i) * HH];
        }
#pragma unroll
        for (int i = 0; i < U; i++) {
            float a = __low2float(cur[i]);
            float bq = __high2float(cur[i]);
            hs = fmaf(a, hs, bq);
            float e  = __expf(-2.f * fabsf(hs));
            float th = __fdividef(1.f - e, 1.f + e);
            __stcs(o + (size_t)(t0 + i) * HH, copysignf(th, hs));
        }
#pragma unroll
        for (int i = 0; i < U; i++) cur[i] = nxt[i];
    }
}

// ---------------------------------------------------------------------------
extern "C" void kernel_launch(void* const* d_in, const int* in_sizes, int n_in,
                              void* d_out, int out_size)
{
    const float* x     = (const float*)d_in[0];
    const float* Wd    = (const float*)d_in[1];
    const float* Wb    = (const float*)d_in[2];
    const float* A_log = (const float*)d_in[3];
    float* out         = (float*)d_out;

    // fused tf32-round + tile pre-pass (exact R13 structure)
    {
        int nt = NTX + 2 * NTW;
        prep_kernel<<<(nt + 255) / 256, 256>>>(x, Wd, Wb);
    }

    cudaFuncSetAttribute(gemm_mma_kernel,
                         cudaFuncAttributeMaxDynamicSharedMemorySize, SMEM_TOTAL);
    dim3 grid(HH / BN, MM / BM);       // (8, 128) = 1024 CTAs
    gemm_mma_kernel<<<grid, NTHR, SMEM_TOTAL>>>(A_log);

    scan_pass3<<<(BB * CHK * HH) / 256, 256>>>(out);
}